// round 1
// baseline (speedup 1.0000x reference)
#include <cuda_runtime.h>

#define NMAX 50000
#define HD 128
#define NG 128
#define NCLS 10

// ---------------- scratch (device globals; no runtime allocation) -----------
__device__ float g_xA[NMAX * HD];
__device__ float g_xB[NMAX * HD];
__device__ float g_agg[NMAX * HD];
__device__ float g_h1[NMAX * HD];
__device__ float g_stats[2 * HD];   // [0:128) col sums, [128:256) col sumsq
__device__ float g_scale[HD];
__device__ float g_shift[HD];
__device__ float g_pool[NG * HD];
__device__ float g_cnt[NG];
__device__ int   g_idx64;           // 1 if indices are int64, 0 if int32

// ---------------- helpers ----------------------------------------------------
__device__ __forceinline__ void red_add_v4(float* p, float4 v) {
    asm volatile("red.global.add.v4.f32 [%0], {%1,%2,%3,%4};"
                 :: "l"(p), "f"(v.x), "f"(v.y), "f"(v.z), "f"(v.w)
                 : "memory");
}

// Detect whether the index buffers are int64 or int32 (JAX without x64 silently
// downcasts). If int64-interpreted values fall in [0, n), it's int64; random
// int32 pairs read as int64 are >= 2^32 with overwhelming probability.
__global__ void detect_idx_kernel(const void* ei, int E, int n) {
    if (threadIdx.x != 0 || blockIdx.x != 0) return;
    const long long* p64 = (const long long*)ei;
    int ok64 = 1;
    for (int i = 0; i < 16; i++) {
        long long v = p64[i];
        if (v < 0 || v >= (long long)n) { ok64 = 0; break; }
    }
    if (ok64) {
        for (int i = 0; i < 16; i++) {
            long long v = p64[(size_t)E + i];
            if (v < 0 || v >= (long long)n) { ok64 = 0; break; }
        }
    }
    g_idx64 = ok64;
}

__device__ __forceinline__ long long load_index(const void* base, long long off, int is64) {
    if (is64) return ((const long long*)base)[off];
    return (long long)((const int*)base)[off];
}

// ---------------- small utility kernels --------------------------------------
__global__ void copy_x_kernel(const float4* __restrict__ src, int n4) {
    float4* dst = reinterpret_cast<float4*>(g_xA);
    for (int i = blockIdx.x * blockDim.x + threadIdx.x; i < n4;
         i += gridDim.x * blockDim.x)
        dst[i] = src[i];
}

__global__ void zero_agg_stats_kernel(int n4) {
    int i = blockIdx.x * blockDim.x + threadIdx.x;
    if (i < 2 * HD) g_stats[i] = 0.f;
    float4 z = make_float4(0.f, 0.f, 0.f, 0.f);
    float4* a = reinterpret_cast<float4*>(g_agg);
    for (int j = i; j < n4; j += gridDim.x * blockDim.x) a[j] = z;
}

__global__ void zero_pool_kernel() {
    int i = blockIdx.x * blockDim.x + threadIdx.x;
    if (i < NG * HD) g_pool[i] = 0.f;
    if (i < NG) g_cnt[i] = 0.f;
}

// ---------------- edge aggregation: agg[dst] += x[src] * ec ------------------
__global__ void edge_agg_kernel(const void* __restrict__ ei,
                                const float* __restrict__ ec,
                                int E, int sel) {
    int e = blockIdx.x * (blockDim.x >> 5) + (threadIdx.x >> 5);
    if (e >= E) return;
    int lane = threadIdx.x & 31;
    int is64 = g_idx64;
    const float* x = sel ? g_xB : g_xA;
    long long s = load_index(ei, e, is64);
    long long d = load_index(ei, (long long)E + e, is64);
    float w = __ldg(ec + e);
    float4 v = *reinterpret_cast<const float4*>(x + s * HD + lane * 4);
    v.x *= w; v.y *= w; v.z *= w; v.w *= w;
    red_add_v4(g_agg + d * HD + lane * 4, v);
}

// ---------------- fused GEMM --------------------------------------------------
// MODE 0: A = x_in + agg * nc[row];  C = h1 = A @ W1 + b1; accumulate col stats
// MODE 1: A = relu(h1 * scale[k] + shift[k]); C = x_out = relu(A @ W2 + b2)
template <int MODE>
__global__ __launch_bounds__(256, 2)
void gemm_kernel(const float* __restrict__ nc,
                 const float* __restrict__ W,
                 const float* __restrict__ bias,
                 int n, int sel) {
    __shared__ float As[16][136];   // [k][row], padded: conflict-free + 16B aligned
    __shared__ float Bs[16][128];   // [k][col]

    const float* Ain;
    float* Cout;
    if (MODE == 0) { Ain = sel ? g_xB : g_xA; Cout = g_h1; }
    else           { Ain = g_h1;              Cout = sel ? g_xB : g_xA; }

    int tid = threadIdx.x;
    int block_row = blockIdx.x * 128;
    int ty = tid >> 4, tx = tid & 15;

    float acc[8][8];
#pragma unroll
    for (int i = 0; i < 8; i++)
#pragma unroll
        for (int j = 0; j < 8; j++) acc[i][j] = 0.f;

    for (int k0 = 0; k0 < 128; k0 += 16) {
#pragma unroll
        for (int t = 0; t < 2; t++) {
            int f = tid + t * 256;          // 0..511 float4 slots of the A tile
            int row = f >> 2;               // 0..127
            int kk = (f & 3) << 2;          // 0,4,8,12
            int grow = block_row + row;
            float4 v = make_float4(0.f, 0.f, 0.f, 0.f);
            if (grow < n) {
                v = *reinterpret_cast<const float4*>(Ain + (size_t)grow * HD + k0 + kk);
                if (MODE == 0) {
                    float w = __ldg(nc + grow);
                    float4 u = *reinterpret_cast<const float4*>(
                        g_agg + (size_t)grow * HD + k0 + kk);
                    v.x = fmaf(u.x, w, v.x);
                    v.y = fmaf(u.y, w, v.y);
                    v.z = fmaf(u.z, w, v.z);
                    v.w = fmaf(u.w, w, v.w);
                } else {
                    int k = k0 + kk;
                    v.x = fmaxf(fmaf(v.x, g_scale[k],     g_shift[k]),     0.f);
                    v.y = fmaxf(fmaf(v.y, g_scale[k + 1], g_shift[k + 1]), 0.f);
                    v.z = fmaxf(fmaf(v.z, g_scale[k + 2], g_shift[k + 2]), 0.f);
                    v.w = fmaxf(fmaf(v.w, g_scale[k + 3], g_shift[k + 3]), 0.f);
                }
            }
            As[kk][row] = v.x;
            As[kk + 1][row] = v.y;
            As[kk + 2][row] = v.z;
            As[kk + 3][row] = v.w;
        }
#pragma unroll
        for (int t = 0; t < 2; t++) {
            int f = tid + t * 256;
            int kr = f >> 5;                // 0..15
            int c = (f & 31) << 2;          // 0..124
            *reinterpret_cast<float4*>(&Bs[kr][c]) =
                *reinterpret_cast<const float4*>(W + (size_t)(k0 + kr) * HD + c);
        }
        __syncthreads();
#pragma unroll
        for (int k = 0; k < 16; k++) {
            float4 a0 = *reinterpret_cast<const float4*>(&As[k][ty * 8]);
            float4 a1 = *reinterpret_cast<const float4*>(&As[k][ty * 8 + 4]);
            float4 b0 = *reinterpret_cast<const float4*>(&Bs[k][tx * 8]);
            float4 b1 = *reinterpret_cast<const float4*>(&Bs[k][tx * 8 + 4]);
            float a[8] = {a0.x, a0.y, a0.z, a0.w, a1.x, a1.y, a1.z, a1.w};
            float b[8] = {b0.x, b0.y, b0.z, b0.w, b1.x, b1.y, b1.z, b1.w};
#pragma unroll
            for (int i = 0; i < 8; i++)
#pragma unroll
                for (int j = 0; j < 8; j++)
                    acc[i][j] = fmaf(a[i], b[j], acc[i][j]);
        }
        __syncthreads();
    }

#pragma unroll
    for (int j = 0; j < 8; j++) {
        int col = tx * 8 + j;
        float bj = __ldg(bias + col);
        if (MODE == 0) {
            float s = 0.f, s2 = 0.f;
#pragma unroll
            for (int i = 0; i < 8; i++) {
                int row = block_row + ty * 8 + i;
                if (row < n) {
                    float v = acc[i][j] + bj;
                    Cout[(size_t)row * HD + col] = v;
                    s += v;
                    s2 += v * v;
                }
            }
            atomicAdd(&g_stats[col], s);
            atomicAdd(&g_stats[HD + col], s2);
        } else {
#pragma unroll
            for (int i = 0; i < 8; i++) {
                int row = block_row + ty * 8 + i;
                if (row < n)
                    Cout[(size_t)row * HD + col] = fmaxf(acc[i][j] + bj, 0.f);
            }
        }
    }
}

// ---------------- BN parameter computation ------------------------------------
__global__ void bn_params_kernel(const float* __restrict__ gamma,
                                 const float* __restrict__ beta, int n) {
    int h = threadIdx.x;
    float invn = 1.f / (float)n;
    float mu = g_stats[h] * invn;
    float var = g_stats[HD + h] * invn - mu * mu;
    float s = gamma[h] * rsqrtf(var + 1e-5f);
    g_scale[h] = s;
    g_shift[h] = beta[h] - mu * s;
}

// ---------------- pooling ------------------------------------------------------
__global__ void pool_kernel(const void* __restrict__ batch, int n, int sel) {
    int i = blockIdx.x * (blockDim.x >> 5) + (threadIdx.x >> 5);
    if (i >= n) return;
    int lane = threadIdx.x & 31;
    int is64 = g_idx64;
    const float* x = sel ? g_xB : g_xA;
    long long g = load_index(batch, i, is64);
    float4 v = *reinterpret_cast<const float4*>(x + (size_t)i * HD + lane * 4);
    red_add_v4(g_pool + g * HD + lane * 4, v);
    if (lane == 0) atomicAdd(&g_cnt[g], 1.f);
}

// ---------------- classifier head ----------------------------------------------
__global__ void head_kernel(const float* __restrict__ Wc,
                            const float* __restrict__ bc,
                            float* __restrict__ out) {
    int g = blockIdx.x;
    int h = threadIdx.x;
    float cnt = g_cnt[g];
    float v = g_pool[g * HD + h] / fmaxf(cnt, 1.f);
    __shared__ float sh[HD];
    for (int c = 0; c < NCLS; c++) {
        sh[h] = v * Wc[h * NCLS + c];
        __syncthreads();
        for (int s = 64; s > 0; s >>= 1) {
            if (h < s) sh[h] += sh[h + s];
            __syncthreads();
        }
        if (h == 0) out[g * NCLS + c] = sh[0] + bc[c];
        __syncthreads();
    }
}

// ---------------- launch ---------------------------------------------------------
extern "C" void kernel_launch(void* const* d_in, const int* in_sizes, int n_in,
                              void* d_out, int out_size) {
    // Detect input ordering: signature order has edge_index (1.6M elems) at [1];
    // setup_inputs dict order has node_centrality (50K) at [1].
    int ix, iei, ib, inc_, iec, iw1, ib1, ig1, ibe1, iw2, ib2, iwc, ibc;
    ix = 0;
    if (n_in >= 13 && in_sizes[1] > 1000000) {
        iei = 1; ib = 2; inc_ = 3; iec = 4;
        iw1 = 5; ib1 = 6; ig1 = 7; ibe1 = 8;
        iw2 = 9; ib2 = 10; iwc = 11; ibc = 12;
    } else {
        inc_ = 1; iec = 2; iw1 = 3; ib1 = 4; ig1 = 5; ibe1 = 6;
        iw2 = 7; ib2 = 8; iwc = 9; ibc = 10; iei = 11; ib = 12;
    }

    const float* x   = (const float*)d_in[ix];
    const void*  ei  = d_in[iei];
    const void*  bat = d_in[ib];
    const float* nc  = (const float*)d_in[inc_];
    const float* ec  = (const float*)d_in[iec];
    const float* W1  = (const float*)d_in[iw1];
    const float* b1  = (const float*)d_in[ib1];
    const float* g1  = (const float*)d_in[ig1];
    const float* be1 = (const float*)d_in[ibe1];
    const float* W2  = (const float*)d_in[iw2];
    const float* b2  = (const float*)d_in[ib2];
    const float* Wc  = (const float*)d_in[iwc];
    const float* bc  = (const float*)d_in[ibc];
    float* out = (float*)d_out;

    int n = in_sizes[ix] / HD;
    int E = in_sizes[iei] / 2;
    int n4 = n * (HD / 4);

    detect_idx_kernel<<<1, 32>>>(ei, E, n);
    copy_x_kernel<<<512, 256>>>((const float4*)x, n4);

    int gemm_blocks = (n + 127) / 128;
    int edge_blocks = (E + 7) / 8;
    int pool_blocks = (n + 7) / 8;

    for (int l = 0; l < 3; l++) {
        int sel_in = l & 1;        // l=0: in A, l=1: in B, l=2: in A
        int sel_out = sel_in ^ 1;
        zero_agg_stats_kernel<<<2048, 256>>>(n4);
        edge_agg_kernel<<<edge_blocks, 256>>>(ei, ec, E, sel_in);
        gemm_kernel<0><<<gemm_blocks, 256>>>(nc, W1 + (size_t)l * HD * HD,
                                             b1 + l * HD, n, sel_in);
        bn_params_kernel<<<1, HD>>>(g1 + l * HD, be1 + l * HD, n);
        gemm_kernel<1><<<gemm_blocks, 256>>>(nullptr, W2 + (size_t)l * HD * HD,
                                             b2 + l * HD, n, sel_out);
    }

    zero_pool_kernel<<<64, 256>>>();
    pool_kernel<<<pool_blocks, 256>>>(bat, n, 1);  // final activations live in g_xB
    head_kernel<<<NG, HD>>>(Wc, bc, out);
}

// round 3
// speedup vs baseline: 3.3018x; 3.3018x over previous
#include <cuda_runtime.h>
#include <cuda_bf16.h>
#include <cstdint>

#define NMAX 50000
#define HD 128
#define NG 128
#define NCLS 10
#define BPAD 136                      // padded row stride (bf16 elems), 272B: conflict-free ldmatrix

// ---------------- scratch (device globals; no runtime allocation) -----------
__device__ float g_xA[NMAX * HD];
__device__ float g_xB[NMAX * HD];
__device__ float g_agg[NMAX * HD];
__device__ float g_h1[NMAX * HD];
__device__ float g_stats[2 * HD];   // [0:128) col sums, [128:256) col sumsq
__device__ float g_scale[HD];
__device__ float g_shift[HD];
__device__ float g_pool[NG * HD];
__device__ float g_cnt[NG];
__device__ int   g_idx64;           // 1 if indices are int64, 0 if int32
// pre-split weights in the padded SMEM image: [k][n], row stride BPAD
__device__ __nv_bfloat16 g_Whi[6][HD * BPAD];
__device__ __nv_bfloat16 g_Wlo[6][HD * BPAD];

// ---------------- helpers -----------------------------------------------------
__device__ __forceinline__ uint32_t smem_u32(const void* p) {
    uint32_t a;
    asm("{ .reg .u64 t; cvta.to.shared.u64 t, %1; cvt.u32.u64 %0, t; }"
        : "=r"(a) : "l"(p));
    return a;
}
__device__ __forceinline__ void red_add_v4(float* p, float4 v) {
    asm volatile("red.global.add.v4.f32 [%0], {%1,%2,%3,%4};"
                 :: "l"(p), "f"(v.x), "f"(v.y), "f"(v.z), "f"(v.w)
                 : "memory");
}
__device__ __forceinline__ uint32_t pack_bf(__nv_bfloat16 a, __nv_bfloat16 b) {
    uint16_t ua = *(uint16_t*)&a, ub = *(uint16_t*)&b;
    return (uint32_t)ua | ((uint32_t)ub << 16);
}
__device__ __forceinline__ void ldmatrix_x4(uint32_t* r, uint32_t addr) {
    asm volatile("ldmatrix.sync.aligned.m8n8.x4.shared.b16 {%0,%1,%2,%3}, [%4];"
                 : "=r"(r[0]), "=r"(r[1]), "=r"(r[2]), "=r"(r[3]) : "r"(addr));
}
__device__ __forceinline__ void ldmatrix_x4_trans(uint32_t* r, uint32_t addr) {
    asm volatile("ldmatrix.sync.aligned.m8n8.x4.trans.shared.b16 {%0,%1,%2,%3}, [%4];"
                 : "=r"(r[0]), "=r"(r[1]), "=r"(r[2]), "=r"(r[3]) : "r"(addr));
}
__device__ __forceinline__ void mma_bf16(float* c, const uint32_t* a, const uint32_t* b) {
    asm volatile(
        "mma.sync.aligned.m16n8k16.row.col.f32.bf16.bf16.f32 "
        "{%0,%1,%2,%3}, {%4,%5,%6,%7}, {%8,%9}, {%0,%1,%2,%3};"
        : "+f"(c[0]), "+f"(c[1]), "+f"(c[2]), "+f"(c[3])
        : "r"(a[0]), "r"(a[1]), "r"(a[2]), "r"(a[3]), "r"(b[0]), "r"(b[1]));
}

// ---------------- index dtype detect ------------------------------------------
__global__ void detect_idx_kernel(const void* ei, int E, int n) {
    if (threadIdx.x != 0 || blockIdx.x != 0) return;
    const long long* p64 = (const long long*)ei;
    int ok64 = 1;
    for (int i = 0; i < 16; i++) {
        long long v = p64[i];
        if (v < 0 || v >= (long long)n) { ok64 = 0; break; }
    }
    if (ok64) {
        for (int i = 0; i < 16; i++) {
            long long v = p64[(size_t)E + i];
            if (v < 0 || v >= (long long)n) { ok64 = 0; break; }
        }
    }
    g_idx64 = ok64;
}
__device__ __forceinline__ long long load_index(const void* base, long long off, int is64) {
    if (is64) return ((const long long*)base)[off];
    return (long long)((const int*)base)[off];
}

// ---------------- small utility kernels --------------------------------------
__global__ void copy_x_kernel(const float4* __restrict__ src, int n4) {
    float4* dst = reinterpret_cast<float4*>(g_xA);
    for (int i = blockIdx.x * blockDim.x + threadIdx.x; i < n4;
         i += gridDim.x * blockDim.x)
        dst[i] = src[i];
}
__global__ void zero_agg_stats_kernel(int n4) {
    int i = blockIdx.x * blockDim.x + threadIdx.x;
    if (i < 2 * HD) g_stats[i] = 0.f;
    float4 z = make_float4(0.f, 0.f, 0.f, 0.f);
    float4* a = reinterpret_cast<float4*>(g_agg);
    for (int j = i; j < n4; j += gridDim.x * blockDim.x) a[j] = z;
}
__global__ void zero_pool_kernel() {
    int i = blockIdx.x * blockDim.x + threadIdx.x;
    if (i < NG * HD) g_pool[i] = 0.f;
    if (i < NG) g_cnt[i] = 0.f;
}

// ---------------- weight pre-split into padded [k][n] image --------------------
__global__ void conv_w_kernel(const float* __restrict__ W, int slot) {
    int i = blockIdx.x * blockDim.x + threadIdx.x;
    if (i >= HD * HD) return;
    int n = i & 127, k = i >> 7;
    float w = W[k * HD + n];
    __nv_bfloat16 hi = __float2bfloat16(w);
    float lof = w - __bfloat162float(hi);
    g_Whi[slot][k * BPAD + n] = hi;
    g_Wlo[slot][k * BPAD + n] = __float2bfloat16(lof);
}

// ---------------- edge aggregation: agg[dst] += x[src] * ec ------------------
__global__ void edge_agg_kernel(const void* __restrict__ ei,
                                const float* __restrict__ ec,
                                int E, int sel) {
    int e = blockIdx.x * (blockDim.x >> 5) + (threadIdx.x >> 5);
    if (e >= E) return;
    int lane = threadIdx.x & 31;
    int is64 = g_idx64;
    const float* x = sel ? g_xB : g_xA;
    long long s = load_index(ei, e, is64);
    long long d = load_index(ei, (long long)E + e, is64);
    float w = __ldg(ec + e);
    float4 v = *reinterpret_cast<const float4*>(x + s * HD + lane * 4);
    v.x *= w; v.y *= w; v.z *= w; v.w *= w;
    red_add_v4(g_agg + d * HD + lane * 4, v);
}

// ---------------- tensor-core bf16x3 fused GEMM --------------------------------
// MODE 0: A = x_in + agg * nc[row];  C = h1 = A @ W1 + b1; accumulate col stats
// MODE 1: A = relu(h1 * scale[k] + shift[k]); C = x_out = relu(A @ W2 + b2)
#define TILE_BYTES (HD * BPAD * 2)          // 34816
#define S_AHI 0
#define S_ALO TILE_BYTES
#define S_BHI (2 * TILE_BYTES)
#define S_BLO (3 * TILE_BYTES)
#define SMEM_SZ (4 * TILE_BYTES)            // 139264

template <int MODE>
__global__ __launch_bounds__(256, 1)
void tgemm_kernel(const float* __restrict__ nc,
                  const float* __restrict__ bias,
                  int n, int sel, int slot) {
    extern __shared__ char smem[];
    uint32_t sb = smem_u32(smem);
    int tid = threadIdx.x, wid = tid >> 5, lane = tid & 31;
    int block_row = blockIdx.x * 128;
    int warp_m = wid & 3;                    // rows warp_m*32
    int warp_n = wid >> 2;                   // cols warp_n*64

    const float* Ain;
    float* Cout;
    if (MODE == 0) { Ain = sel ? g_xB : g_xA; Cout = g_h1; }
    else           { Ain = g_h1;              Cout = sel ? g_xB : g_xA; }

    // ---- copy pre-split W tiles (already padded image) ----
    {
        const uint4* wh = (const uint4*)g_Whi[slot];
        const uint4* wl = (const uint4*)g_Wlo[slot];
        uint4* dh = (uint4*)(smem + S_BHI);
        uint4* dl = (uint4*)(smem + S_BLO);
        for (int i = tid; i < TILE_BYTES / 16; i += 256) {
            dh[i] = wh[i];
            dl[i] = wl[i];
        }
    }

    // ---- fused A producer: load, fuse, bf16 hi/lo split ----
#pragma unroll 4
    for (int it = 0; it < 16; it++) {
        int f = tid + it * 256;              // 0..4095 float4 slots
        int row = f >> 5;                    // 0..127
        int kk = (f & 31) << 2;              // 0..124
        int grow = block_row + row;
        float4 v = make_float4(0.f, 0.f, 0.f, 0.f);
        if (grow < n) {
            v = *reinterpret_cast<const float4*>(Ain + (size_t)grow * HD + kk);
            if (MODE == 0) {
                float w = __ldg(nc + grow);
                float4 u = *reinterpret_cast<const float4*>(g_agg + (size_t)grow * HD + kk);
                v.x = fmaf(u.x, w, v.x);
                v.y = fmaf(u.y, w, v.y);
                v.z = fmaf(u.z, w, v.z);
                v.w = fmaf(u.w, w, v.w);
            } else {
                float4 sc = *reinterpret_cast<const float4*>(g_scale + kk);
                float4 sh = *reinterpret_cast<const float4*>(g_shift + kk);
                v.x = fmaxf(fmaf(v.x, sc.x, sh.x), 0.f);
                v.y = fmaxf(fmaf(v.y, sc.y, sh.y), 0.f);
                v.z = fmaxf(fmaf(v.z, sc.z, sh.z), 0.f);
                v.w = fmaxf(fmaf(v.w, sc.w, sh.w), 0.f);
            }
        }
        __nv_bfloat16 h0 = __float2bfloat16(v.x);
        __nv_bfloat16 h1 = __float2bfloat16(v.y);
        __nv_bfloat16 h2 = __float2bfloat16(v.z);
        __nv_bfloat16 h3 = __float2bfloat16(v.w);
        __nv_bfloat16 l0 = __float2bfloat16(v.x - __bfloat162float(h0));
        __nv_bfloat16 l1 = __float2bfloat16(v.y - __bfloat162float(h1));
        __nv_bfloat16 l2 = __float2bfloat16(v.z - __bfloat162float(h2));
        __nv_bfloat16 l3 = __float2bfloat16(v.w - __bfloat162float(h3));
        uint2 hp; hp.x = pack_bf(h0, h1); hp.y = pack_bf(h2, h3);
        uint2 lp; lp.x = pack_bf(l0, l1); lp.y = pack_bf(l2, l3);
        int off = row * (BPAD * 2) + kk * 2;     // bytes
        *(uint2*)(smem + S_AHI + off) = hp;
        *(uint2*)(smem + S_ALO + off) = lp;
    }
    __syncthreads();

    // ---- MMA mainloop: 8 k-steps, 3 products, fp32 accumulate ----
    float acc[2][8][4];
#pragma unroll
    for (int mf = 0; mf < 2; mf++)
#pragma unroll
        for (int nf = 0; nf < 8; nf++)
#pragma unroll
            for (int q = 0; q < 4; q++) acc[mf][nf][q] = 0.f;

    // per-lane ldmatrix base offsets
    int lrow = lane & 15;                    // matrix row
    int lblk = (lane >> 4) * 16;             // +16B for second 8-col block
    uint32_t aBase = sb + (warp_m * 32 + lrow) * (BPAD * 2) + lblk;
    uint32_t bBase = sb + lrow * (BPAD * 2) + (warp_n * 64) * 2 + lblk;

#pragma unroll
    for (int ks = 0; ks < 8; ks++) {
        uint32_t ah[2][4], al[2][4], bh[8][2], bl[8][2];
#pragma unroll
        for (int mf = 0; mf < 2; mf++) {
            uint32_t addr = aBase + mf * 16 * (BPAD * 2) + ks * 32;
            ldmatrix_x4(ah[mf], addr + S_AHI);
            ldmatrix_x4(al[mf], addr + S_ALO);
        }
#pragma unroll
        for (int nb = 0; nb < 4; nb++) {
            uint32_t addr = bBase + ks * 16 * (BPAD * 2) + nb * 32;
            uint32_t rh[4], rl[4];
            ldmatrix_x4_trans(rh, addr + S_BHI);
            ldmatrix_x4_trans(rl, addr + S_BLO);
            bh[2 * nb][0] = rh[0]; bh[2 * nb][1] = rh[1];
            bh[2 * nb + 1][0] = rh[2]; bh[2 * nb + 1][1] = rh[3];
            bl[2 * nb][0] = rl[0]; bl[2 * nb][1] = rl[1];
            bl[2 * nb + 1][0] = rl[2]; bl[2 * nb + 1][1] = rl[3];
        }
#pragma unroll
        for (int mf = 0; mf < 2; mf++)
#pragma unroll
            for (int nf = 0; nf < 8; nf++) {
                mma_bf16(acc[mf][nf], ah[mf], bh[nf]);
                mma_bf16(acc[mf][nf], ah[mf], bl[nf]);
                mma_bf16(acc[mf][nf], al[mf], bh[nf]);
            }
    }

    // ---- epilogue: bias, (stats | relu), direct fragment stores ----
    int r0 = block_row + warp_m * 32 + (lane >> 2);   // rows r0, r0+8, r0+16, r0+24
#pragma unroll
    for (int nf = 0; nf < 8; nf++) {
        int col = warp_n * 64 + nf * 8 + (lane & 3) * 2;
        float b0 = __ldg(bias + col), b1 = __ldg(bias + col + 1);
        float v[4][2];
#pragma unroll
        for (int mf = 0; mf < 2; mf++) {
            v[mf * 2][0] = acc[mf][nf][0] + b0;
            v[mf * 2][1] = acc[mf][nf][1] + b1;
            v[mf * 2 + 1][0] = acc[mf][nf][2] + b0;
            v[mf * 2 + 1][1] = acc[mf][nf][3] + b1;
        }
        bool val[4];
        val[0] = r0 < n; val[1] = r0 + 8 < n; val[2] = r0 + 16 < n; val[3] = r0 + 24 < n;
        if (MODE == 0) {
            float s0 = 0.f, s1 = 0.f, q0 = 0.f, q1 = 0.f;
#pragma unroll
            for (int p = 0; p < 4; p++) {
                if (val[p]) {
                    s0 += v[p][0]; q0 += v[p][0] * v[p][0];
                    s1 += v[p][1]; q1 += v[p][1] * v[p][1];
                }
            }
#pragma unroll
            for (int d = 4; d < 32; d <<= 1) {
                s0 += __shfl_xor_sync(0xFFFFFFFFu, s0, d);
                s1 += __shfl_xor_sync(0xFFFFFFFFu, s1, d);
                q0 += __shfl_xor_sync(0xFFFFFFFFu, q0, d);
                q1 += __shfl_xor_sync(0xFFFFFFFFu, q1, d);
            }
            if (lane < 4) {
                int c0 = warp_n * 64 + nf * 8 + lane * 2;
                atomicAdd(&g_stats[c0], s0);
                atomicAdd(&g_stats[c0 + 1], s1);
                atomicAdd(&g_stats[HD + c0], q0);
                atomicAdd(&g_stats[HD + c0 + 1], q1);
            }
        } else {
#pragma unroll
            for (int p = 0; p < 4; p++) {
                v[p][0] = fmaxf(v[p][0], 0.f);
                v[p][1] = fmaxf(v[p][1], 0.f);
            }
        }
        // stores: rows r0 + {0,8,16,24}
#pragma unroll
        for (int p = 0; p < 4; p++) {
            int row = r0 + ((p & 1) ? 8 : 0) + ((p >> 1) ? 16 : 0);
            int pi = (p & 1) + (p >> 1) * 2;   // map store order to v index
            if (row < n) {
                float2 o = make_float2(v[pi][0], v[pi][1]);
                *reinterpret_cast<float2*>(Cout + (size_t)row * HD + col) = o;
            }
        }
    }
}

// ---------------- BN parameter computation ------------------------------------
__global__ void bn_params_kernel(const float* __restrict__ gamma,
                                 const float* __restrict__ beta, int n) {
    int h = threadIdx.x;
    float invn = 1.f / (float)n;
    float mu = g_stats[h] * invn;
    float var = g_stats[HD + h] * invn - mu * mu;
    float s = gamma[h] * rsqrtf(var + 1e-5f);
    g_scale[h] = s;
    g_shift[h] = beta[h] - mu * s;
}

// ---------------- pooling ------------------------------------------------------
__global__ void pool_kernel(const void* __restrict__ batch, int n, int sel) {
    int i = blockIdx.x * (blockDim.x >> 5) + (threadIdx.x >> 5);
    if (i >= n) return;
    int lane = threadIdx.x & 31;
    int is64 = g_idx64;
    const float* x = sel ? g_xB : g_xA;
    long long g = load_index(batch, i, is64);
    float4 v = *reinterpret_cast<const float4*>(x + (size_t)i * HD + lane * 4);
    red_add_v4(g_pool + g * HD + lane * 4, v);
    if (lane == 0) atomicAdd(&g_cnt[g], 1.f);
}

// ---------------- classifier head ----------------------------------------------
__global__ void head_kernel(const float* __restrict__ Wc,
                            const float* __restrict__ bc,
                            float* __restrict__ out) {
    int g = blockIdx.x;
    int h = threadIdx.x;
    float cnt = g_cnt[g];
    float v = g_pool[g * HD + h] / fmaxf(cnt, 1.f);
    __shared__ float sh[HD];
    for (int c = 0; c < NCLS; c++) {
        sh[h] = v * Wc[h * NCLS + c];
        __syncthreads();
        for (int s = 64; s > 0; s >>= 1) {
            if (h < s) sh[h] += sh[h + s];
            __syncthreads();
        }
        if (h == 0) out[g * NCLS + c] = sh[0] + bc[c];
        __syncthreads();
    }
}

// ---------------- launch ---------------------------------------------------------
extern "C" void kernel_launch(void* const* d_in, const int* in_sizes, int n_in,
                              void* d_out, int out_size) {
    cudaFuncSetAttribute(tgemm_kernel<0>,
                         cudaFuncAttributeMaxDynamicSharedMemorySize, SMEM_SZ);
    cudaFuncSetAttribute(tgemm_kernel<1>,
                         cudaFuncAttributeMaxDynamicSharedMemorySize, SMEM_SZ);

    // Detect input ordering: signature order has edge_index (1.6M elems) at [1];
    // setup_inputs dict order has node_centrality (50K) at [1].
    int ix, iei, ib, inc_, iec, iw1, ib1, ig1, ibe1, iw2, ib2, iwc, ibc;
    ix = 0;
    if (n_in >= 13 && in_sizes[1] > 1000000) {
        iei = 1; ib = 2; inc_ = 3; iec = 4;
        iw1 = 5; ib1 = 6; ig1 = 7; ibe1 = 8;
        iw2 = 9; ib2 = 10; iwc = 11; ibc = 12;
    } else {
        inc_ = 1; iec = 2; iw1 = 3; ib1 = 4; ig1 = 5; ibe1 = 6;
        iw2 = 7; ib2 = 8; iwc = 9; ibc = 10; iei = 11; ib = 12;
    }

    const float* x   = (const float*)d_in[ix];
    const void*  ei  = d_in[iei];
    const void*  bat = d_in[ib];
    const float* nc  = (const float*)d_in[inc_];
    const float* ec  = (const float*)d_in[iec];
    const float* W1  = (const float*)d_in[iw1];
    const float* b1  = (const float*)d_in[ib1];
    const float* g1  = (const float*)d_in[ig1];
    const float* be1 = (const float*)d_in[ibe1];
    const float* W2  = (const float*)d_in[iw2];
    const float* b2  = (const float*)d_in[ib2];
    const float* Wc  = (const float*)d_in[iwc];
    const float* bc  = (const float*)d_in[ibc];
    float* out = (float*)d_out;

    int n = in_sizes[ix] / HD;
    int E = in_sizes[iei] / 2;
    int n4 = n * (HD / 4);

    detect_idx_kernel<<<1, 32>>>(ei, E, n);
    copy_x_kernel<<<512, 256>>>((const float4*)x, n4);
    for (int l = 0; l < 3; l++) {
        conv_w_kernel<<<64, 256>>>(W1 + (size_t)l * HD * HD, l);
        conv_w_kernel<<<64, 256>>>(W2 + (size_t)l * HD * HD, 3 + l);
    }

    int gemm_blocks = (n + 127) / 128;
    int edge_blocks = (E + 7) / 8;
    int pool_blocks = (n + 7) / 8;

    for (int l = 0; l < 3; l++) {
        int sel_in = l & 1;        // l=0: in A, l=1: in B, l=2: in A
        int sel_out = sel_in ^ 1;
        zero_agg_stats_kernel<<<2048, 256>>>(n4);
        edge_agg_kernel<<<edge_blocks, 256>>>(ei, ec, E, sel_in);
        tgemm_kernel<0><<<gemm_blocks, 256, SMEM_SZ>>>(nc, b1 + l * HD, n, sel_in, l);
        bn_params_kernel<<<1, HD>>>(g1 + l * HD, be1 + l * HD, n);
        tgemm_kernel<1><<<gemm_blocks, 256, SMEM_SZ>>>(nullptr, b2 + l * HD, n, sel_out, 3 + l);
    }

    zero_pool_kernel<<<64, 256>>>();
    pool_kernel<<<pool_blocks, 256>>>(bat, n, 1);  // final activations live in g_xB
    head_kernel<<<NG, HD>>>(Wc, bc, out);
}